// round 1
// baseline (speedup 1.0000x reference)
#include <cuda_runtime.h>
#include <cuda_bf16.h>
#include <math.h>

// Problem dims
#define BATCH 64
#define SEQ   512
#define HID   768
#define ATTH  100
#define CLSH  300

#define NTOK (BATCH*SEQ)          // 32768
#define HS_ELEMS (BATCH*SEQ*HID)  // 25165824

// Output layout (flattened tuple):
// [0..4]  loss, sentence_loss, token_loss, reg_a, reg_b
// [5 .. 5+HS_ELEMS)            hidden_states echo
// [.. +NTOK)                   masked
// [.. +BATCH)                  sent
#define OUT_HID_OFF  5
#define OUT_MASK_OFF (5 + HS_ELEMS)
#define OUT_SENT_OFF (5 + HS_ELEMS + NTOK)

// ---------------- device scratch (no allocs allowed) ----------------
__device__ float g_token_att[NTOK];
__device__ float g_pooled[BATCH*HID];
__device__ float g_sum[BATCH];
__device__ float g_maxm[BATCH];
__device__ float g_minm[BATCH];
__device__ float g_slab[BATCH];
__device__ float g_tl[BATCH];
__device__ float g_sent[BATCH];

// =====================================================================
// Kernel 1: fused token-attention head.
// token_att[m] = sigmoid( sum_j tanh( (A@W1)[m,j] + b1[j] ) * W2[j] + b2 )
// Tile: 64 tokens x 128 cols (100 valid) per block, K-chunks of 32.
// =====================================================================
#define MT 64
#define KT 32

__global__ void __launch_bounds__(256)
att_gemm_kernel(const float* __restrict__ A,
                const float* __restrict__ W1,
                const float* __restrict__ b1,
                const float* __restrict__ W2,
                const float* __restrict__ b2,
                float* __restrict__ tok)
{
    __shared__ float A_sh[MT][KT + 1];
    __shared__ float W_sh[KT][128];

    const int tid = threadIdx.x;
    const int tx  = tid & 31;   // col lane
    const int ty  = tid >> 5;   // warp id: owns tokens ty*8 .. ty*8+7
    const int m0  = blockIdx.x * MT;

    float acc[8][4];
#pragma unroll
    for (int r = 0; r < 8; r++)
#pragma unroll
        for (int c = 0; c < 4; c++) acc[r][c] = 0.f;

    for (int k0 = 0; k0 < HID; k0 += KT) {
        __syncthreads();
        // Load A tile: 64x32, coalesced (lane = k)
#pragma unroll
        for (int i = 0; i < 8; i++) {
            int e = i * 256 + tid;
            int m = e >> 5;
            int k = e & 31;
            A_sh[m][k] = A[(size_t)(m0 + m) * HID + k0 + k];
        }
        // Load W1 tile: 32x100 (pad cols 100..127 unused; guarded in epilogue)
#pragma unroll
        for (int i = 0; i < 13; i++) {
            int e = i * 256 + tid;
            if (e < KT * ATTH) {
                int k = e / ATTH;
                int j = e - k * ATTH;
                W_sh[k][j] = W1[(size_t)(k0 + k) * ATTH + j];
            }
        }
        // zero-fill pad columns to keep acc finite
        if (tid < KT * 4) {
            int k = tid >> 2;
            W_sh[k][100 + (tid & 3)] = 0.f;
        }
        __syncthreads();

#pragma unroll
        for (int k = 0; k < KT; k++) {
            float w0 = W_sh[k][tx];
            float w1 = W_sh[k][tx + 32];
            float w2 = W_sh[k][tx + 64];
            float w3 = W_sh[k][tx + 96];
#pragma unroll
            for (int r = 0; r < 8; r++) {
                float a = A_sh[ty * 8 + r][k];   // broadcast
                acc[r][0] += a * w0;
                acc[r][1] += a * w1;
                acc[r][2] += a * w2;
                acc[r][3] += a * w3;
            }
        }
    }

    // Epilogue: tanh, dot with W2, warp-reduce, sigmoid
    float w2v[4], b1v[4];
#pragma unroll
    for (int c = 0; c < 4; c++) {
        int j = tx + 32 * c;
        if (j < ATTH) { w2v[c] = W2[j]; b1v[c] = b1[j]; }
        else          { w2v[c] = 0.f;   b1v[c] = 0.f;   }
    }
    const float bias2 = b2[0];

#pragma unroll
    for (int r = 0; r < 8; r++) {
        float p = 0.f;
#pragma unroll
        for (int c = 0; c < 4; c++) {
            int j = tx + 32 * c;
            if (j < ATTH) p += tanhf(acc[r][c] + b1v[c]) * w2v[c];
        }
#pragma unroll
        for (int o = 16; o > 0; o >>= 1)
            p += __shfl_xor_sync(0xffffffffu, p, o);
        if (tx == 0) {
            float x = p + bias2;
            tok[m0 + ty * 8 + r] = 1.f / (1.f + expf(-x));
        }
    }
}

// =====================================================================
// Kernel 2: segment-max over subwords + mask + per-row stats.
// One block per batch row, 512 threads.
// =====================================================================
__global__ void __launch_bounds__(512)
seg_mask_kernel(const int* __restrict__ off,
                const float* __restrict__ labels,
                const float* __restrict__ tok,
                float* __restrict__ out_masked)
{
    const int b = blockIdx.x;
    const int s = threadIdx.x;
    const int base = b * SEQ;

    float lab  = labels[base + s];
    bool  cont = (off[(size_t)(base + s) * 2] != 0);

    float masked = 0.f;
    if (!cont) {
        float wa = tok[base + s];
        int t = s + 1;
        while (t < SEQ && off[(size_t)(base + t) * 2] != 0) {
            wa = fmaxf(wa, tok[base + t]);
            t++;
        }
        if (lab != -1.0f) masked = wa;
    }
    out_masked[base + s] = masked;

    float z    = (lab == 1.0f) ? 1.0f : 0.0f;
    float tl   = (masked - z) * (masked - z);
    float ones = (masked == 0.f) ? 1.f : masked;

    __shared__ float sh[512];

    // sum(masked)
    sh[s] = masked; __syncthreads();
    for (int st = 256; st > 0; st >>= 1) { if (s < st) sh[s] += sh[s + st]; __syncthreads(); }
    if (s == 0) g_sum[b] = sh[0];
    __syncthreads();

    // max(masked)
    sh[s] = masked; __syncthreads();
    for (int st = 256; st > 0; st >>= 1) { if (s < st) sh[s] = fmaxf(sh[s], sh[s + st]); __syncthreads(); }
    if (s == 0) g_maxm[b] = sh[0];
    __syncthreads();

    // min(ones_mask)
    sh[s] = ones; __syncthreads();
    for (int st = 256; st > 0; st >>= 1) { if (s < st) sh[s] = fminf(sh[s], sh[s + st]); __syncthreads(); }
    if (s == 0) g_minm[b] = sh[0];
    __syncthreads();

    // max(labels) -> sentence label
    sh[s] = lab; __syncthreads();
    for (int st = 256; st > 0; st >>= 1) { if (s < st) sh[s] = fmaxf(sh[s], sh[s + st]); __syncthreads(); }
    if (s == 0) g_slab[b] = sh[0];
    __syncthreads();

    // sum token loss
    sh[s] = tl; __syncthreads();
    for (int st = 256; st > 0; st >>= 1) { if (s < st) sh[s] += sh[s + st]; __syncthreads(); }
    if (s == 0) g_tl[b] = sh[0];
}

// =====================================================================
// Kernel 3: soft-attention pooling. grid (BATCH, HID/256), 256 threads.
// pooled[b,h] = (sum_s hs[b,s,h] * masked[b,s]) / sum_masked[b]
// =====================================================================
__global__ void __launch_bounds__(256)
pool_kernel(const float* __restrict__ hs,
            const float* __restrict__ masked,
            float* __restrict__ pooled)
{
    const int b = blockIdx.x;
    const int h = blockIdx.y * 256 + threadIdx.x;

    __shared__ float nm[SEQ];
    for (int i = threadIdx.x; i < SEQ; i += 256)
        nm[i] = masked[b * SEQ + i];
    __syncthreads();

    const float inv = 1.0f / g_sum[b];
    const float* hp = hs + (size_t)b * SEQ * HID + h;

    float acc = 0.f;
#pragma unroll 4
    for (int s = 0; s < SEQ; s++)
        acc += hp[(size_t)s * HID] * nm[s];

    pooled[b * HID + h] = acc * inv;
}

// =====================================================================
// Kernel 4: sentence head. One block per batch row, 128 threads.
// sent = sigmoid( sum_j tanh( (pooled@W3)[j] + b3[j] ) * W4[j] + b4 )
// =====================================================================
__global__ void __launch_bounds__(128)
sent_kernel(const float* __restrict__ pooled,
            const float* __restrict__ W3,
            const float* __restrict__ b3,
            const float* __restrict__ W4,
            const float* __restrict__ b4,
            float* __restrict__ out_sent)
{
    const int b = blockIdx.x;
    const int tid = threadIdx.x;

    __shared__ float pl[HID];
    for (int i = tid; i < HID; i += 128) pl[i] = pooled[b * HID + i];
    __syncthreads();

    float part = 0.f;
    for (int j = tid; j < CLSH; j += 128) {
        float acc = b3[j];
        for (int k = 0; k < HID; k++)
            acc += pl[k] * W3[(size_t)k * CLSH + j];
        part += tanhf(acc) * W4[j];
    }

    __shared__ float red[128];
    red[tid] = part; __syncthreads();
    for (int st = 64; st > 0; st >>= 1) { if (tid < st) red[tid] += red[tid + st]; __syncthreads(); }

    if (tid == 0) {
        float sv = 1.f / (1.f + expf(-(red[0] + b4[0])));
        g_sent[b] = sv;
        out_sent[b] = sv;
    }
}

// =====================================================================
// Kernel 5: finalize losses. 1 block, 64 threads.
// =====================================================================
__global__ void __launch_bounds__(64)
final_kernel(float* __restrict__ out)
{
    const int b = threadIdx.x;
    float sl = g_sent[b] - g_slab[b]; sl *= sl;
    float ra = g_minm[b] * g_minm[b];
    float d  = g_maxm[b] - g_slab[b]; float rb = d * d;
    float tl = g_tl[b];

    __shared__ float s1[64], s2[64], s3[64], s4[64];
    s1[b] = sl; s2[b] = tl; s3[b] = ra; s4[b] = rb;
    __syncthreads();
    for (int st = 32; st > 0; st >>= 1) {
        if (b < st) { s1[b] += s1[b+st]; s2[b] += s2[b+st]; s3[b] += s3[b+st]; s4[b] += s4[b+st]; }
        __syncthreads();
    }
    if (b == 0) {
        float sentence = s1[0], token = s2[0], rega = s3[0], regb = s4[0];
        out[0] = sentence + token + 0.01f * (rega + regb);
        out[1] = sentence;
        out[2] = token;
        out[3] = rega;
        out[4] = regb;
    }
}

// =====================================================================
extern "C" void kernel_launch(void* const* d_in, const int* in_sizes, int n_in,
                              void* d_out, int out_size)
{
    const float* hs     = (const float*)d_in[0];
    const int*   off    = (const int*)  d_in[1];
    const float* labels = (const float*)d_in[2];
    const float* W1     = (const float*)d_in[3];
    const float* b1     = (const float*)d_in[4];
    const float* W2     = (const float*)d_in[5];
    const float* b2     = (const float*)d_in[6];
    const float* W3     = (const float*)d_in[7];
    const float* b3     = (const float*)d_in[8];
    const float* W4     = (const float*)d_in[9];
    const float* b4     = (const float*)d_in[10];

    float* out = (float*)d_out;
    float* out_hidden = out + OUT_HID_OFF;
    float* out_masked = out + OUT_MASK_OFF;
    float* out_sent   = out + OUT_SENT_OFF;

    float* tok;     cudaGetSymbolAddress((void**)&tok,     g_token_att);
    float* pooled;  cudaGetSymbolAddress((void**)&pooled,  g_pooled);

    // Echo hidden_states (overlaps with compute on same stream order; D2D async)
    cudaMemcpyAsync(out_hidden, hs, (size_t)HS_ELEMS * sizeof(float),
                    cudaMemcpyDeviceToDevice);

    // Stage A: fused token attention head (the big one)
    att_gemm_kernel<<<NTOK / MT, 256>>>(hs, W1, b1, W2, b2, tok);

    // Stage B: segment max, mask, row stats
    seg_mask_kernel<<<BATCH, SEQ>>>(off, labels, tok, out_masked);

    // Stage C: pooling
    dim3 pg(BATCH, HID / 256);
    pool_kernel<<<pg, 256>>>(hs, out_masked, pooled);

    // Stage D: sentence head
    sent_kernel<<<BATCH, 128>>>(pooled, W3, b3, W4, b4, out_sent);

    // Stage E: losses
    final_kernel<<<1, 64>>>(out);
}

// round 2
// speedup vs baseline: 1.0448x; 1.0448x over previous
#include <cuda_runtime.h>
#include <cuda_bf16.h>
#include <math.h>

// Problem dims
#define BATCH 64
#define SEQ   512
#define HID   768
#define ATTH  100
#define CLSH  300

#define NTOK (BATCH*SEQ)          // 32768
#define HS_ELEMS (BATCH*SEQ*HID)  // 25165824

// Output layout
#define OUT_HID_OFF  5
#define OUT_MASK_OFF (5 + HS_ELEMS)
#define OUT_SENT_OFF (5 + HS_ELEMS + NTOK)

// ---------------- device scratch ----------------
__device__ float g_token_att[NTOK];
__device__ float g_pooled[BATCH*HID];
__device__ float g_sum[BATCH];
__device__ float g_maxm[BATCH];
__device__ float g_minm[BATCH];
__device__ float g_slab[BATCH];
__device__ float g_tl[BATCH];
__device__ float g_sent[BATCH];

// packed f32x2 FMA (Blackwell): d = a*b + d, two fp32 lanes per instruction
__device__ __forceinline__ void fma_f32x2(unsigned long long& d,
                                          unsigned long long a,
                                          unsigned long long b) {
    asm("fma.rn.f32x2 %0, %1, %2, %0;" : "+l"(d) : "l"(a), "l"(b));
}
__device__ __forceinline__ unsigned long long pack_dup(float x) {
    unsigned long long r; unsigned u = __float_as_uint(x);
    asm("mov.b64 %0, {%1, %1};" : "=l"(r) : "r"(u));
    return r;
}
__device__ __forceinline__ void unpack2(float& lo, float& hi, unsigned long long v) {
    unsigned a, b;
    asm("mov.b64 {%0, %1}, %2;" : "=r"(a), "=r"(b) : "l"(v));
    lo = __uint_as_float(a); hi = __uint_as_float(b);
}

// =====================================================================
// Kernel 1: fused token-attention head with FFMA2 inner product.
// Tile: 64 tokens x 128 cols (100 valid), KT=32, register-prefetch pipeline.
// Thread (ty,tx): warp ty owns tokens ty*8..+7; lane tx owns cols 4tx..4tx+3.
// =====================================================================
#define MT 64
#define KT 32
#define KCH (HID / KT)   // 24

__global__ void __launch_bounds__(256)
att_gemm_kernel(const float* __restrict__ A,
                const float* __restrict__ W1,
                const float* __restrict__ b1,
                const float* __restrict__ W2,
                const float* __restrict__ b2,
                float* __restrict__ tok)
{
    __shared__ float  A_sh[KT][MT + 1];   // k-major, +1 pad (scalar broadcast reads)
    __shared__ float4 W_sh4[KT][32];      // [k][jj] -> cols 4jj..4jj+3 (jj<25 valid)

    const int tid = threadIdx.x;
    const int tx  = tid & 31;
    const int ty  = tid >> 5;
    const int m0  = blockIdx.x * MT;

    unsigned long long acc01[8], acc23[8];
#pragma unroll
    for (int r = 0; r < 8; r++) { acc01[r] = 0ull; acc23[r] = 0ull; }

    // ---- prefetch registers ----
    float4 aR[2];
    float4 wR[4];

    // A tile: 64x32 = 512 float4; thread handles f = i*256+tid
    auto loadA = [&](int k0) {
#pragma unroll
        for (int i = 0; i < 2; i++) {
            int f = i * 256 + tid;
            int m = f >> 3;
            int kk = (f & 7) << 2;
            aR[i] = *reinterpret_cast<const float4*>(&A[(size_t)(m0 + m) * HID + k0 + kk]);
        }
    };
    // W1 tile: 32 rows x 25 float4 = 800 float4
    auto loadW = [&](int k0) {
#pragma unroll
        for (int i = 0; i < 4; i++) {
            int e = i * 256 + tid;
            if (e < KT * 25) {
                int k = e / 25;
                int jj = e - k * 25;
                wR[i] = *reinterpret_cast<const float4*>(&W1[(size_t)(k0 + k) * ATTH + jj * 4]);
            }
        }
    };
    auto storeTiles = [&]() {
#pragma unroll
        for (int i = 0; i < 2; i++) {
            int f = i * 256 + tid;
            int m = f >> 3;
            int kk = (f & 7) << 2;
            A_sh[kk + 0][m] = aR[i].x;
            A_sh[kk + 1][m] = aR[i].y;
            A_sh[kk + 2][m] = aR[i].z;
            A_sh[kk + 3][m] = aR[i].w;
        }
#pragma unroll
        for (int i = 0; i < 4; i++) {
            int e = i * 256 + tid;
            if (e < KT * 25) {
                int k = e / 25;
                int jj = e - k * 25;
                W_sh4[k][jj] = wR[i];
            }
        }
    };

    loadA(0); loadW(0);

    for (int kc = 0; kc < KCH; kc++) {
        storeTiles();
        __syncthreads();
        if (kc + 1 < KCH) { loadA((kc + 1) * KT); loadW((kc + 1) * KT); }

#pragma unroll
        for (int k = 0; k < KT; k++) {
            float4 w = W_sh4[k][tx];
            unsigned long long w01 = *reinterpret_cast<unsigned long long*>(&w.x);
            unsigned long long w23 = *reinterpret_cast<unsigned long long*>(&w.z);
            const float* arow = &A_sh[k][ty * 8];
#pragma unroll
            for (int r = 0; r < 8; r++) {
                unsigned long long aa = pack_dup(arow[r]);
                fma_f32x2(acc01[r], aa, w01);
                fma_f32x2(acc23[r], aa, w23);
            }
        }
        __syncthreads();
    }

    // Epilogue: cols j = 4tx..4tx+3, valid iff tx < 25
    const float bias2 = b2[0];
    float w2v[4], b1v[4];
    if (tx < 25) {
#pragma unroll
        for (int c = 0; c < 4; c++) { w2v[c] = W2[4 * tx + c]; b1v[c] = b1[4 * tx + c]; }
    }

#pragma unroll
    for (int r = 0; r < 8; r++) {
        float p = 0.f;
        if (tx < 25) {
            float a0, a1, a2, a3;
            unpack2(a0, a1, acc01[r]);
            unpack2(a2, a3, acc23[r]);
            p  = tanhf(a0 + b1v[0]) * w2v[0];
            p += tanhf(a1 + b1v[1]) * w2v[1];
            p += tanhf(a2 + b1v[2]) * w2v[2];
            p += tanhf(a3 + b1v[3]) * w2v[3];
        }
#pragma unroll
        for (int o = 16; o > 0; o >>= 1)
            p += __shfl_xor_sync(0xffffffffu, p, o);
        if (tx == 0) {
            float x = p + bias2;
            tok[m0 + ty * 8 + r] = 1.f / (1.f + expf(-x));
        }
    }
}

// =====================================================================
// Kernel 2: segment-max + mask + per-row stats. One block per batch row.
// =====================================================================
__global__ void __launch_bounds__(512)
seg_mask_kernel(const int* __restrict__ off,
                const float* __restrict__ labels,
                const float* __restrict__ tok,
                float* __restrict__ out_masked)
{
    const int b = blockIdx.x;
    const int s = threadIdx.x;
    const int base = b * SEQ;

    float lab  = labels[base + s];
    bool  cont = (off[(size_t)(base + s) * 2] != 0);

    float masked = 0.f;
    if (!cont) {
        float wa = tok[base + s];
        int t = s + 1;
        while (t < SEQ && off[(size_t)(base + t) * 2] != 0) {
            wa = fmaxf(wa, tok[base + t]);
            t++;
        }
        if (lab != -1.0f) masked = wa;
    }
    out_masked[base + s] = masked;

    float z    = (lab == 1.0f) ? 1.0f : 0.0f;
    float tl   = (masked - z) * (masked - z);
    float ones = (masked == 0.f) ? 1.f : masked;

    __shared__ float sh[512];

    sh[s] = masked; __syncthreads();
    for (int st = 256; st > 0; st >>= 1) { if (s < st) sh[s] += sh[s + st]; __syncthreads(); }
    if (s == 0) g_sum[b] = sh[0];
    __syncthreads();

    sh[s] = masked; __syncthreads();
    for (int st = 256; st > 0; st >>= 1) { if (s < st) sh[s] = fmaxf(sh[s], sh[s + st]); __syncthreads(); }
    if (s == 0) g_maxm[b] = sh[0];
    __syncthreads();

    sh[s] = ones; __syncthreads();
    for (int st = 256; st > 0; st >>= 1) { if (s < st) sh[s] = fminf(sh[s], sh[s + st]); __syncthreads(); }
    if (s == 0) g_minm[b] = sh[0];
    __syncthreads();

    sh[s] = lab; __syncthreads();
    for (int st = 256; st > 0; st >>= 1) { if (s < st) sh[s] = fmaxf(sh[s], sh[s + st]); __syncthreads(); }
    if (s == 0) g_slab[b] = sh[0];
    __syncthreads();

    sh[s] = tl; __syncthreads();
    for (int st = 256; st > 0; st >>= 1) { if (s < st) sh[s] += sh[s + st]; __syncthreads(); }
    if (s == 0) g_tl[b] = sh[0];
}

// =====================================================================
// Kernel 3: pooling + hidden_states echo (fused: one read pass serves both).
// grid (BATCH, HID/256), 256 threads.
// =====================================================================
__global__ void __launch_bounds__(256)
pool_kernel(const float* __restrict__ hs,
            const float* __restrict__ masked,
            float* __restrict__ pooled,
            float* __restrict__ out_hidden)
{
    const int b = blockIdx.x;
    const int h = blockIdx.y * 256 + threadIdx.x;

    __shared__ float nm[SEQ];
    for (int i = threadIdx.x; i < SEQ; i += 256)
        nm[i] = masked[b * SEQ + i];
    __syncthreads();

    const float inv = 1.0f / g_sum[b];
    const float* hp = hs + (size_t)b * SEQ * HID + h;
    float* op = out_hidden + (size_t)b * SEQ * HID + h;

    float acc = 0.f;
#pragma unroll 4
    for (int s = 0; s < SEQ; s++) {
        float v = hp[(size_t)s * HID];
        op[(size_t)s * HID] = v;        // echo
        acc += v * nm[s];
    }

    pooled[b * HID + h] = acc * inv;
}

// =====================================================================
// Kernel 4: sentence head. One block per batch row, 384 threads (col j = tid).
// =====================================================================
__global__ void __launch_bounds__(384)
sent_kernel(const float* __restrict__ pooled,
            const float* __restrict__ W3,
            const float* __restrict__ b3,
            const float* __restrict__ W4,
            const float* __restrict__ b4,
            float* __restrict__ out_sent)
{
    const int b = blockIdx.x;
    const int tid = threadIdx.x;

    __shared__ float pl[HID];
    for (int i = tid; i < HID; i += 384) pl[i] = pooled[b * HID + i];
    __syncthreads();

    float part = 0.f;
    if (tid < CLSH) {
        float acc = b3[tid];
        const float* wcol = W3 + tid;
#pragma unroll 8
        for (int k = 0; k < HID; k++)
            acc += pl[k] * wcol[(size_t)k * CLSH];
        part = tanhf(acc) * W4[tid];
    }

    __shared__ float red[512];
    red[tid] = part;
    if (tid < 128) red[384 + tid] = 0.f;
    __syncthreads();
    for (int st = 256; st > 0; st >>= 1) {
        if (tid < st) red[tid] += red[tid + st];
        __syncthreads();
    }

    if (tid == 0) {
        float sv = 1.f / (1.f + expf(-(red[0] + b4[0])));
        g_sent[b] = sv;
        out_sent[b] = sv;
    }
}

// =====================================================================
// Kernel 5: finalize losses.
// =====================================================================
__global__ void __launch_bounds__(64)
final_kernel(float* __restrict__ out)
{
    const int b = threadIdx.x;
    float sl = g_sent[b] - g_slab[b]; sl *= sl;
    float ra = g_minm[b] * g_minm[b];
    float d  = g_maxm[b] - g_slab[b]; float rb = d * d;
    float tl = g_tl[b];

    __shared__ float s1[64], s2[64], s3[64], s4[64];
    s1[b] = sl; s2[b] = tl; s3[b] = ra; s4[b] = rb;
    __syncthreads();
    for (int st = 32; st > 0; st >>= 1) {
        if (b < st) { s1[b] += s1[b+st]; s2[b] += s2[b+st]; s3[b] += s3[b+st]; s4[b] += s4[b+st]; }
        __syncthreads();
    }
    if (b == 0) {
        float sentence = s1[0], token = s2[0], rega = s3[0], regb = s4[0];
        out[0] = sentence + token + 0.01f * (rega + regb);
        out[1] = sentence;
        out[2] = token;
        out[3] = rega;
        out[4] = regb;
    }
}

// =====================================================================
extern "C" void kernel_launch(void* const* d_in, const int* in_sizes, int n_in,
                              void* d_out, int out_size)
{
    const float* hs     = (const float*)d_in[0];
    const int*   off    = (const int*)  d_in[1];
    const float* labels = (const float*)d_in[2];
    const float* W1     = (const float*)d_in[3];
    const float* b1     = (const float*)d_in[4];
    const float* W2     = (const float*)d_in[5];
    const float* b2     = (const float*)d_in[6];
    const float* W3     = (const float*)d_in[7];
    const float* b3     = (const float*)d_in[8];
    const float* W4     = (const float*)d_in[9];
    const float* b4     = (const float*)d_in[10];

    float* out = (float*)d_out;
    float* out_hidden = out + OUT_HID_OFF;
    float* out_masked = out + OUT_MASK_OFF;
    float* out_sent   = out + OUT_SENT_OFF;

    float* tok;     cudaGetSymbolAddress((void**)&tok,     g_token_att);
    float* pooled;  cudaGetSymbolAddress((void**)&pooled,  g_pooled);

    // Stage A: fused token attention head (FFMA2)
    att_gemm_kernel<<<NTOK / MT, 256>>>(hs, W1, b1, W2, b2, tok);

    // Stage B: segment max, mask, row stats
    seg_mask_kernel<<<BATCH, SEQ>>>(off, labels, tok, out_masked);

    // Stage C: pooling + hidden echo (single hs read pass)
    dim3 pg(BATCH, HID / 256);
    pool_kernel<<<pg, 256>>>(hs, out_masked, pooled, out_hidden);

    // Stage D: sentence head
    sent_kernel<<<BATCH, 384>>>(pooled, W3, b3, W4, b4, out_sent);

    // Stage E: losses
    final_kernel<<<1, 64>>>(out);
}

// round 3
// speedup vs baseline: 1.4258x; 1.3646x over previous
#include <cuda_runtime.h>
#include <cuda_bf16.h>
#include <math.h>

// Problem dims
#define BATCH 64
#define SEQ   512
#define HID   768
#define ATTH  100
#define CLSH  300

#define NTOK (BATCH*SEQ)          // 32768
#define HS_ELEMS (BATCH*SEQ*HID)  // 25165824

// Output layout
#define OUT_HID_OFF  5
#define OUT_MASK_OFF (5 + HS_ELEMS)
#define OUT_SENT_OFF (5 + HS_ELEMS + NTOK)

// ---------------- device scratch ----------------
__device__ float g_token_att[NTOK];
__device__ float g_pooled[BATCH*HID];
__device__ float g_sum[BATCH];
__device__ float g_maxm[BATCH];
__device__ float g_minm[BATCH];
__device__ float g_slab[BATCH];
__device__ float g_tl[BATCH];
__device__ float g_sent_part[BATCH*5];

__device__ __forceinline__ unsigned f2tf32(float x) {
    unsigned r;
    asm("cvt.rna.tf32.f32 %0, %1;" : "=r"(r) : "f"(x));
    return r;
}

__device__ __forceinline__ void mma_tf32(float& d0, float& d1, float& d2, float& d3,
                                         unsigned a0, unsigned a1, unsigned a2, unsigned a3,
                                         unsigned b0, unsigned b1) {
    asm volatile(
        "mma.sync.aligned.m16n8k8.row.col.f32.tf32.tf32.f32 "
        "{%0,%1,%2,%3}, {%4,%5,%6,%7}, {%8,%9}, {%0,%1,%2,%3};"
        : "+f"(d0), "+f"(d1), "+f"(d2), "+f"(d3)
        : "r"(a0), "r"(a1), "r"(a2), "r"(a3), "r"(b0), "r"(b1));
}

// =====================================================================
// Kernel 1: fused token-attention head on TF32 tensor cores.
// C[32768,100] = hs[32768,768] @ W1[768,100], then tanh, @W2, sigmoid.
// Block: 256 threads (8 warps), tile 128 tokens x 104 cols (100 valid).
// K chunks of 32 (4 mma k-steps each). 256 blocks.
// =====================================================================
#define MT   128
#define KT   32
#define NPAD 104
#define NT   13            // n-tiles of 8
#define KCH  (HID / KT)    // 24
#define ASTR 36            // A_sh row stride (conflict-free: (4q+r4)%32 distinct)

__global__ void __launch_bounds__(256)
att_gemm_kernel(const float* __restrict__ A,
                const float* __restrict__ W1,
                const float* __restrict__ b1,
                const float* __restrict__ W2,
                const float* __restrict__ b2,
                float* __restrict__ tok)
{
    __shared__ unsigned A_sh[MT][ASTR];      // [row][k], tf32 bits
    __shared__ unsigned W_sh[KT][NPAD];      // [k][j],  tf32 bits

    const int tid = threadIdx.x;
    const int lane = tid & 31;
    const int wid  = tid >> 5;               // 0..7, warp owns rows wid*16..+15
    const int q    = lane >> 2;              // 0..7
    const int r4   = lane & 3;               // 0..3
    const int m0   = blockIdx.x * MT;
    const int wr   = wid * 16;

    float acc[NT][4];
#pragma unroll
    for (int nt = 0; nt < NT; nt++)
#pragma unroll
        for (int c = 0; c < 4; c++) acc[nt][c] = 0.f;

    // prefetch regs
    float4 aR[2];          // A: 128x32 = 4096 fl = 1024 float4 / 256 thr = 4... use 2x float4 x2? -> 4 float4
    float4 aR2[2];
    float  wR[13];

    auto loadA = [&](int k0) {
#pragma unroll
        for (int i = 0; i < 2; i++) {
            int f = i * 256 + tid;           // 0..511
            int row = f >> 3;                // 0..63
            int kk  = (f & 7) << 2;
            aR[i]  = *reinterpret_cast<const float4*>(&A[(size_t)(m0 + row) * HID + k0 + kk]);
            aR2[i] = *reinterpret_cast<const float4*>(&A[(size_t)(m0 + row + 64) * HID + k0 + kk]);
        }
    };
    auto loadW = [&](int k0) {
#pragma unroll
        for (int i = 0; i < 13; i++) {
            int e = i * 256 + tid;
            if (e < KT * ATTH) {
                int k = e / ATTH;
                int j = e - k * ATTH;
                wR[i] = W1[(size_t)(k0 + k) * ATTH + j];
            }
        }
    };
    auto storeTiles = [&]() {
#pragma unroll
        for (int i = 0; i < 2; i++) {
            int f = i * 256 + tid;
            int row = f >> 3;
            int kk  = (f & 7) << 2;
            A_sh[row][kk+0] = f2tf32(aR[i].x);
            A_sh[row][kk+1] = f2tf32(aR[i].y);
            A_sh[row][kk+2] = f2tf32(aR[i].z);
            A_sh[row][kk+3] = f2tf32(aR[i].w);
            A_sh[row+64][kk+0] = f2tf32(aR2[i].x);
            A_sh[row+64][kk+1] = f2tf32(aR2[i].y);
            A_sh[row+64][kk+2] = f2tf32(aR2[i].z);
            A_sh[row+64][kk+3] = f2tf32(aR2[i].w);
        }
#pragma unroll
        for (int i = 0; i < 13; i++) {
            int e = i * 256 + tid;
            if (e < KT * ATTH) {
                int k = e / ATTH;
                int j = e - k * ATTH;
                W_sh[k][j] = f2tf32(wR[i]);
            }
        }
        // zero pad cols 100..103
        if (tid < KT * 4) {
            int k = tid >> 2;
            W_sh[k][ATTH + (tid & 3)] = 0u;
        }
    };

    loadA(0); loadW(0);

    for (int kc = 0; kc < KCH; kc++) {
        storeTiles();
        __syncthreads();
        if (kc + 1 < KCH) { loadA((kc + 1) * KT); loadW((kc + 1) * KT); }

#pragma unroll
        for (int ks = 0; ks < 4; ks++) {
            const int k = ks * 8;
            unsigned a0 = A_sh[wr + q     ][k + r4];
            unsigned a1 = A_sh[wr + q + 8 ][k + r4];
            unsigned a2 = A_sh[wr + q     ][k + r4 + 4];
            unsigned a3 = A_sh[wr + q + 8 ][k + r4 + 4];
#pragma unroll
            for (int nt = 0; nt < NT; nt++) {
                unsigned b0 = W_sh[k + r4    ][nt * 8 + q];
                unsigned b1f = W_sh[k + r4 + 4][nt * 8 + q];
                mma_tf32(acc[nt][0], acc[nt][1], acc[nt][2], acc[nt][3],
                         a0, a1, a2, a3, b0, b1f);
            }
        }
        __syncthreads();
    }

    // Epilogue: thread owns rows (wr+q, wr+q+8), cols j = nt*8 + 2*r4 + {0,1}
    const float bias2 = b2[0];
    float p0 = 0.f, p1 = 0.f;
#pragma unroll
    for (int nt = 0; nt < NT; nt++) {
        int j0 = nt * 8 + 2 * r4;
        int j1 = j0 + 1;
        float bb0 = 0.f, bb1 = 0.f, ww0 = 0.f, ww1 = 0.f;
        if (j0 < ATTH) { bb0 = b1[j0]; ww0 = W2[j0]; }
        if (j1 < ATTH) { bb1 = b1[j1]; ww1 = W2[j1]; }
        p0 += tanhf(acc[nt][0] + bb0) * ww0 + tanhf(acc[nt][1] + bb1) * ww1;
        p1 += tanhf(acc[nt][2] + bb0) * ww0 + tanhf(acc[nt][3] + bb1) * ww1;
    }
    // reduce across the 4 lanes of the quad (r4 dimension)
#pragma unroll
    for (int o = 1; o <= 2; o <<= 1) {
        p0 += __shfl_xor_sync(0xffffffffu, p0, o);
        p1 += __shfl_xor_sync(0xffffffffu, p1, o);
    }
    if (r4 == 0) {
        int m = m0 + wr + q;
        tok[m]     = 1.f / (1.f + expf(-(p0 + bias2)));
        tok[m + 8] = 1.f / (1.f + expf(-(p1 + bias2)));
    }
}

// =====================================================================
// Kernel 2: segment-max + mask + per-row stats. One block per batch row.
// =====================================================================
__global__ void __launch_bounds__(512)
seg_mask_kernel(const int* __restrict__ off,
                const float* __restrict__ labels,
                const float* __restrict__ tok,
                float* __restrict__ out_masked)
{
    const int b = blockIdx.x;
    const int s = threadIdx.x;
    const int base = b * SEQ;

    float lab  = labels[base + s];
    bool  cont = (off[(size_t)(base + s) * 2] != 0);

    float masked = 0.f;
    if (!cont) {
        float wa = tok[base + s];
        int t = s + 1;
        while (t < SEQ && off[(size_t)(base + t) * 2] != 0) {
            wa = fmaxf(wa, tok[base + t]);
            t++;
        }
        if (lab != -1.0f) masked = wa;
    }
    out_masked[base + s] = masked;

    float z    = (lab == 1.0f) ? 1.0f : 0.0f;
    float tl   = (masked - z) * (masked - z);
    float ones = (masked == 0.f) ? 1.f : masked;

    __shared__ float sh[512];

    sh[s] = masked; __syncthreads();
    for (int st = 256; st > 0; st >>= 1) { if (s < st) sh[s] += sh[s + st]; __syncthreads(); }
    if (s == 0) g_sum[b] = sh[0];
    __syncthreads();

    sh[s] = masked; __syncthreads();
    for (int st = 256; st > 0; st >>= 1) { if (s < st) sh[s] = fmaxf(sh[s], sh[s + st]); __syncthreads(); }
    if (s == 0) g_maxm[b] = sh[0];
    __syncthreads();

    sh[s] = ones; __syncthreads();
    for (int st = 256; st > 0; st >>= 1) { if (s < st) sh[s] = fminf(sh[s], sh[s + st]); __syncthreads(); }
    if (s == 0) g_minm[b] = sh[0];
    __syncthreads();

    sh[s] = lab; __syncthreads();
    for (int st = 256; st > 0; st >>= 1) { if (s < st) sh[s] = fmaxf(sh[s], sh[s + st]); __syncthreads(); }
    if (s == 0) g_slab[b] = sh[0];
    __syncthreads();

    sh[s] = tl; __syncthreads();
    for (int st = 256; st > 0; st >>= 1) { if (s < st) sh[s] += sh[s + st]; __syncthreads(); }
    if (s == 0) g_tl[b] = sh[0];
}

// =====================================================================
// Kernel 3: pooling + hidden_states echo (one read pass serves both).
// =====================================================================
__global__ void __launch_bounds__(256)
pool_kernel(const float* __restrict__ hs,
            const float* __restrict__ masked,
            float* __restrict__ pooled,
            float* __restrict__ out_hidden)
{
    const int b = blockIdx.x;
    const int h = blockIdx.y * 256 + threadIdx.x;

    __shared__ float nm[SEQ];
    for (int i = threadIdx.x; i < SEQ; i += 256)
        nm[i] = masked[b * SEQ + i];
    __syncthreads();

    const float inv = 1.0f / g_sum[b];
    const float* hp = hs + (size_t)b * SEQ * HID + h;
    float* op = out_hidden + (size_t)b * SEQ * HID + h;

    float acc = 0.f;
#pragma unroll 4
    for (int s = 0; s < SEQ; s++) {
        float v = hp[(size_t)s * HID];
        op[(size_t)s * HID] = v;        // echo
        acc += v * nm[s];
    }

    pooled[b * HID + h] = acc * inv;
}

// =====================================================================
// Kernel 4: sentence head, split-j + split-k for parallelism.
// grid (BATCH, 5): block handles 60 cols x 4 k-splits (240 threads of 256).
// Writes deterministic partial sums to g_sent_part[b*5 + jb].
// =====================================================================
__global__ void __launch_bounds__(256)
sent_kernel(const float* __restrict__ pooled,
            const float* __restrict__ W3,
            const float* __restrict__ b3,
            const float* __restrict__ W4)
{
    const int b   = blockIdx.x;
    const int jb  = blockIdx.y;
    const int tid = threadIdx.x;

    __shared__ float pl[HID];
    for (int i = tid; i < HID; i += 256) pl[i] = pooled[b * HID + i];
    __syncthreads();

    __shared__ float part[60][4];
    __shared__ float red[64];

    if (tid < 240) {
        const int jl = tid % 60;
        const int ks = tid / 60;          // 0..3
        const int j  = jb * 60 + jl;
        const int k0 = ks * 192;
        const float* wcol = W3 + (size_t)k0 * CLSH + j;
        float acc = 0.f;
#pragma unroll 8
        for (int k = 0; k < 192; k++)
            acc += pl[k0 + k] * wcol[(size_t)k * CLSH];
        part[jl][ks] = acc;
    }
    __syncthreads();

    float v = 0.f;
    if (tid < 60) {
        const int j = jb * 60 + tid;
        float s = part[tid][0] + part[tid][1] + part[tid][2] + part[tid][3];
        v = tanhf(s + b3[j]) * W4[j];
    }
    if (tid < 64) red[tid] = (tid < 60) ? v : 0.f;
    __syncthreads();
    for (int st = 32; st > 0; st >>= 1) {
        if (tid < st) red[tid] += red[tid + st];
        __syncthreads();
    }
    if (tid == 0) g_sent_part[b * 5 + jb] = red[0];
}

// =====================================================================
// Kernel 5: finalize sent + losses.
// =====================================================================
__global__ void __launch_bounds__(64)
final_kernel(const float* __restrict__ b4,
             float* __restrict__ out,
             float* __restrict__ out_sent)
{
    const int b = threadIdx.x;

    float pre = b4[0];
#pragma unroll
    for (int i = 0; i < 5; i++) pre += g_sent_part[b * 5 + i];
    float sv = 1.f / (1.f + expf(-pre));
    out_sent[b] = sv;

    float sl = sv - g_slab[b]; sl *= sl;
    float ra = g_minm[b] * g_minm[b];
    float d  = g_maxm[b] - g_slab[b]; float rb = d * d;
    float tl = g_tl[b];

    __shared__ float s1[64], s2[64], s3[64], s4[64];
    s1[b] = sl; s2[b] = tl; s3[b] = ra; s4[b] = rb;
    __syncthreads();
    for (int st = 32; st > 0; st >>= 1) {
        if (b < st) { s1[b] += s1[b+st]; s2[b] += s2[b+st]; s3[b] += s3[b+st]; s4[b] += s4[b+st]; }
        __syncthreads();
    }
    if (b == 0) {
        float sentence = s1[0], token = s2[0], rega = s3[0], regb = s4[0];
        out[0] = sentence + token + 0.01f * (rega + regb);
        out[1] = sentence;
        out[2] = token;
        out[3] = rega;
        out[4] = regb;
    }
}

// =====================================================================
extern "C" void kernel_launch(void* const* d_in, const int* in_sizes, int n_in,
                              void* d_out, int out_size)
{
    const float* hs     = (const float*)d_in[0];
    const int*   off    = (const int*)  d_in[1];
    const float* labels = (const float*)d_in[2];
    const float* W1     = (const float*)d_in[3];
    const float* b1     = (const float*)d_in[4];
    const float* W2     = (const float*)d_in[5];
    const float* b2     = (const float*)d_in[6];
    const float* W3     = (const float*)d_in[7];
    const float* b3     = (const float*)d_in[8];
    const float* W4     = (const float*)d_in[9];
    const float* b4     = (const float*)d_in[10];

    float* out = (float*)d_out;
    float* out_hidden = out + OUT_HID_OFF;
    float* out_masked = out + OUT_MASK_OFF;
    float* out_sent   = out + OUT_SENT_OFF;

    float* tok;     cudaGetSymbolAddress((void**)&tok,     g_token_att);
    float* pooled;  cudaGetSymbolAddress((void**)&pooled,  g_pooled);

    // Stage A: token attention head on TF32 tensor cores
    att_gemm_kernel<<<NTOK / MT, 256>>>(hs, W1, b1, W2, b2, tok);

    // Stage B: segment max, mask, row stats
    seg_mask_kernel<<<BATCH, SEQ>>>(off, labels, tok, out_masked);

    // Stage C: pooling + hidden echo
    dim3 pg(BATCH, HID / 256);
    pool_kernel<<<pg, 256>>>(hs, out_masked, pooled, out_hidden);

    // Stage D: sentence head (parallel partials)
    dim3 sg(BATCH, 5);
    sent_kernel<<<sg, 256>>>(pooled, W3, b3, W4);

    // Stage E: sent finalize + losses
    final_kernel<<<1, 64>>>(b4, out, out_sent);
}

// round 5
// speedup vs baseline: 2.8229x; 1.9799x over previous
#include <cuda_runtime.h>
#include <cuda_bf16.h>
#include <math.h>

// Problem dims
#define BATCH 64
#define SEQ   512
#define HID   768
#define ATTH  100
#define CLSH  300

#define NTOK (BATCH*SEQ)          // 32768
#define HS_ELEMS (BATCH*SEQ*HID)  // 25165824

// Output layout
#define OUT_HID_OFF  5
#define OUT_MASK_OFF (5 + HS_ELEMS)
#define OUT_SENT_OFF (5 + HS_ELEMS + NTOK)

// ---------------- device scratch ----------------
__device__ float g_token_att[NTOK];
__device__ float g_pool_part[4 * BATCH * HID];      // s-split partial pooled (unnormalized)
__device__ float g_sent_j[BATCH * 8 * CLSH];        // k-split partial preacts
__device__ float g_sum[BATCH];
__device__ float g_maxm[BATCH];
__device__ float g_minm[BATCH];
__device__ float g_slab[BATCH];
__device__ float g_tl[BATCH];
__device__ float g_sent[BATCH];

__device__ __forceinline__ unsigned f2tf32(float x) {
    unsigned r;
    asm("cvt.rna.tf32.f32 %0, %1;" : "=r"(r) : "f"(x));
    return r;
}

__device__ __forceinline__ void mma_tf32(float& d0, float& d1, float& d2, float& d3,
                                         unsigned a0, unsigned a1, unsigned a2, unsigned a3,
                                         unsigned b0, unsigned b1) {
    asm volatile(
        "mma.sync.aligned.m16n8k8.row.col.f32.tf32.tf32.f32 "
        "{%0,%1,%2,%3}, {%4,%5,%6,%7}, {%8,%9}, {%0,%1,%2,%3};"
        : "+f"(d0), "+f"(d1), "+f"(d2), "+f"(d3)
        : "r"(a0), "r"(a1), "r"(a2), "r"(a3), "r"(b0), "r"(b1));
}

// alignment-safe 4-float store (out_hidden is only 4-byte aligned: base = d_out+5 floats)
__device__ __forceinline__ void store4_scalar(float* p, float4 v) {
    p[0] = v.x; p[1] = v.y; p[2] = v.z; p[3] = v.w;
}

// =====================================================================
// Kernel 1: fused token-attention head on TF32 tensor cores + hs echo.
// =====================================================================
#define MT   128
#define KT   32
#define NPAD 104
#define NT   13
#define KCH  (HID / KT)    // 24
#define ASTR 36

__global__ void __launch_bounds__(256)
att_gemm_kernel(const float* __restrict__ A,
                const float* __restrict__ W1,
                const float* __restrict__ b1,
                const float* __restrict__ W2,
                const float* __restrict__ b2,
                float* __restrict__ tok,
                float* __restrict__ out_hidden)
{
    __shared__ unsigned A_sh[MT][ASTR];
    __shared__ unsigned W_sh[KT][NPAD];

    const int tid = threadIdx.x;
    const int lane = tid & 31;
    const int wid  = tid >> 5;
    const int q    = lane >> 2;
    const int r4   = lane & 3;
    const int m0   = blockIdx.x * MT;
    const int wr   = wid * 16;

    float acc[NT][4];
#pragma unroll
    for (int nt = 0; nt < NT; nt++)
#pragma unroll
        for (int c = 0; c < 4; c++) acc[nt][c] = 0.f;

    float4 aR[2], aR2[2];
    float  wR[13];

    auto loadA = [&](int k0) {
#pragma unroll
        for (int i = 0; i < 2; i++) {
            int f = i * 256 + tid;
            int row = f >> 3;
            int kk  = (f & 7) << 2;
            aR[i]  = *reinterpret_cast<const float4*>(&A[(size_t)(m0 + row) * HID + k0 + kk]);
            aR2[i] = *reinterpret_cast<const float4*>(&A[(size_t)(m0 + row + 64) * HID + k0 + kk]);
        }
    };
    auto loadW = [&](int k0) {
#pragma unroll
        for (int i = 0; i < 13; i++) {
            int e = i * 256 + tid;
            if (e < KT * ATTH) {
                int k = e / ATTH;
                int j = e - k * ATTH;
                wR[i] = W1[(size_t)(k0 + k) * ATTH + j];
            }
        }
    };
    auto storeTiles = [&](int k0) {
#pragma unroll
        for (int i = 0; i < 2; i++) {
            int f = i * 256 + tid;
            int row = f >> 3;
            int kk  = (f & 7) << 2;
            A_sh[row][kk+0] = f2tf32(aR[i].x);
            A_sh[row][kk+1] = f2tf32(aR[i].y);
            A_sh[row][kk+2] = f2tf32(aR[i].z);
            A_sh[row][kk+3] = f2tf32(aR[i].w);
            A_sh[row+64][kk+0] = f2tf32(aR2[i].x);
            A_sh[row+64][kk+1] = f2tf32(aR2[i].y);
            A_sh[row+64][kk+2] = f2tf32(aR2[i].z);
            A_sh[row+64][kk+3] = f2tf32(aR2[i].w);
            // echo hidden_states — SCALAR stores (out_hidden is only 4B-aligned)
            store4_scalar(&out_hidden[(size_t)(m0 + row) * HID + k0 + kk], aR[i]);
            store4_scalar(&out_hidden[(size_t)(m0 + row + 64) * HID + k0 + kk], aR2[i]);
        }
#pragma unroll
        for (int i = 0; i < 13; i++) {
            int e = i * 256 + tid;
            if (e < KT * ATTH) {
                int k = e / ATTH;
                int j = e - k * ATTH;
                W_sh[k][j] = f2tf32(wR[i]);
            }
        }
        if (tid < KT * 4) {
            int k = tid >> 2;
            W_sh[k][ATTH + (tid & 3)] = 0u;
        }
    };

    loadA(0); loadW(0);

    for (int kc = 0; kc < KCH; kc++) {
        storeTiles(kc * KT);
        __syncthreads();
        if (kc + 1 < KCH) { loadA((kc + 1) * KT); loadW((kc + 1) * KT); }

#pragma unroll
        for (int ks = 0; ks < 4; ks++) {
            const int k = ks * 8;
            unsigned a0 = A_sh[wr + q     ][k + r4];
            unsigned a1 = A_sh[wr + q + 8 ][k + r4];
            unsigned a2 = A_sh[wr + q     ][k + r4 + 4];
            unsigned a3 = A_sh[wr + q + 8 ][k + r4 + 4];
#pragma unroll
            for (int nt = 0; nt < NT; nt++) {
                unsigned b0  = W_sh[k + r4    ][nt * 8 + q];
                unsigned b1f = W_sh[k + r4 + 4][nt * 8 + q];
                mma_tf32(acc[nt][0], acc[nt][1], acc[nt][2], acc[nt][3],
                         a0, a1, a2, a3, b0, b1f);
            }
        }
        __syncthreads();
    }

    const float bias2 = b2[0];
    float p0 = 0.f, p1 = 0.f;
#pragma unroll
    for (int nt = 0; nt < NT; nt++) {
        int j0 = nt * 8 + 2 * r4;
        int j1 = j0 + 1;
        float bb0 = 0.f, bb1 = 0.f, ww0 = 0.f, ww1 = 0.f;
        if (j0 < ATTH) { bb0 = b1[j0]; ww0 = W2[j0]; }
        if (j1 < ATTH) { bb1 = b1[j1]; ww1 = W2[j1]; }
        p0 += tanhf(acc[nt][0] + bb0) * ww0 + tanhf(acc[nt][1] + bb1) * ww1;
        p1 += tanhf(acc[nt][2] + bb0) * ww0 + tanhf(acc[nt][3] + bb1) * ww1;
    }
#pragma unroll
    for (int o = 1; o <= 2; o <<= 1) {
        p0 += __shfl_xor_sync(0xffffffffu, p0, o);
        p1 += __shfl_xor_sync(0xffffffffu, p1, o);
    }
    if (r4 == 0) {
        int m = m0 + wr + q;
        tok[m]     = 1.f / (1.f + expf(-(p0 + bias2)));
        tok[m + 8] = 1.f / (1.f + expf(-(p1 + bias2)));
    }
}

// =====================================================================
// Kernel 2: segment-max + mask + per-row stats.
// =====================================================================
__global__ void __launch_bounds__(512)
seg_mask_kernel(const int* __restrict__ off,
                const float* __restrict__ labels,
                const float* __restrict__ tok,
                float* __restrict__ out_masked)
{
    const int b = blockIdx.x;
    const int s = threadIdx.x;
    const int base = b * SEQ;

    float lab  = labels[base + s];
    bool  cont = (off[(size_t)(base + s) * 2] != 0);

    float masked = 0.f;
    if (!cont) {
        float wa = tok[base + s];
        int t = s + 1;
        while (t < SEQ && off[(size_t)(base + t) * 2] != 0) {
            wa = fmaxf(wa, tok[base + t]);
            t++;
        }
        if (lab != -1.0f) masked = wa;
    }
    out_masked[base + s] = masked;

    float z    = (lab == 1.0f) ? 1.0f : 0.0f;
    float tl   = (masked - z) * (masked - z);
    float ones = (masked == 0.f) ? 1.f : masked;

    __shared__ float sh[512];

    sh[s] = masked; __syncthreads();
    for (int st = 256; st > 0; st >>= 1) { if (s < st) sh[s] += sh[s + st]; __syncthreads(); }
    if (s == 0) g_sum[b] = sh[0];
    __syncthreads();

    sh[s] = masked; __syncthreads();
    for (int st = 256; st > 0; st >>= 1) { if (s < st) sh[s] = fmaxf(sh[s], sh[s + st]); __syncthreads(); }
    if (s == 0) g_maxm[b] = sh[0];
    __syncthreads();

    sh[s] = ones; __syncthreads();
    for (int st = 256; st > 0; st >>= 1) { if (s < st) sh[s] = fminf(sh[s], sh[s + st]); __syncthreads(); }
    if (s == 0) g_minm[b] = sh[0];
    __syncthreads();

    sh[s] = lab; __syncthreads();
    for (int st = 256; st > 0; st >>= 1) { if (s < st) sh[s] = fmaxf(sh[s], sh[s + st]); __syncthreads(); }
    if (s == 0) g_slab[b] = sh[0];
    __syncthreads();

    sh[s] = tl; __syncthreads();
    for (int st = 256; st > 0; st >>= 1) { if (s < st) sh[s] += sh[s + st]; __syncthreads(); }
    if (s == 0) g_tl[b] = sh[0];
}

// =====================================================================
// Kernel 3: pooling partials. grid (BATCH, 4 s-chunks), 192 threads.
// =====================================================================
__global__ void __launch_bounds__(192)
pool_kernel(const float* __restrict__ hs,
            const float* __restrict__ masked)
{
    const int b  = blockIdx.x;
    const int ss = blockIdx.y;
    const int tid = threadIdx.x;
    const int s0 = ss * 128;

    __shared__ float nm[128];
    if (tid < 128) nm[tid] = masked[b * SEQ + s0 + tid];
    __syncthreads();

    const float4* hp = reinterpret_cast<const float4*>(
        hs + (size_t)b * SEQ * HID + (size_t)s0 * HID) + tid;

    float4 acc = make_float4(0.f, 0.f, 0.f, 0.f);
#pragma unroll 8
    for (int s = 0; s < 128; s++) {
        float4 v = hp[(size_t)s * (HID / 4)];
        float w = nm[s];
        acc.x += v.x * w; acc.y += v.y * w;
        acc.z += v.z * w; acc.w += v.w * w;
    }

    float4* dst = reinterpret_cast<float4*>(
        g_pool_part + ((size_t)ss * BATCH + b) * HID) + tid;
    *dst = acc;
}

// =====================================================================
// Kernel 4: sentence head split-k partials. grid (BATCH, 8), 320 threads.
// =====================================================================
__global__ void __launch_bounds__(320)
sent_part_kernel(const float* __restrict__ W3)
{
    const int b  = blockIdx.x;
    const int ks = blockIdx.y;
    const int tid = threadIdx.x;
    const int k0 = ks * 96;

    __shared__ float pl[96];
    if (tid < 96) {
        const int h = k0 + tid;
        float v = g_pool_part[(size_t)(0 * BATCH + b) * HID + h]
                + g_pool_part[(size_t)(1 * BATCH + b) * HID + h]
                + g_pool_part[(size_t)(2 * BATCH + b) * HID + h]
                + g_pool_part[(size_t)(3 * BATCH + b) * HID + h];
        pl[tid] = v / g_sum[b];
    }
    __syncthreads();

    if (tid < CLSH) {
        const float* wp = W3 + (size_t)k0 * CLSH + tid;
        float a0 = 0.f, a1 = 0.f;
#pragma unroll 8
        for (int k = 0; k < 96; k += 2) {
            a0 += pl[k]     * wp[(size_t)k * CLSH];
            a1 += pl[k + 1] * wp[(size_t)(k + 1) * CLSH];
        }
        g_sent_j[((size_t)b * 8 + ks) * CLSH + tid] = a0 + a1;
    }
}

// =====================================================================
// Kernel 5: sentence combine. grid (BATCH), 320 threads.
// =====================================================================
__global__ void __launch_bounds__(320)
sent_comb_kernel(const float* __restrict__ b3,
                 const float* __restrict__ W4,
                 const float* __restrict__ b4,
                 float* __restrict__ out_sent)
{
    const int b = blockIdx.x;
    const int tid = threadIdx.x;

    float v = 0.f;
    if (tid < CLSH) {
        float s = b3[tid];
#pragma unroll
        for (int ks = 0; ks < 8; ks++)
            s += g_sent_j[((size_t)b * 8 + ks) * CLSH + tid];
        v = tanhf(s) * W4[tid];
    }

    __shared__ float red[512];
    red[tid] = v;
    if (tid + 320 < 512) red[tid + 320] = 0.f;
    __syncthreads();
    for (int st = 256; st > 0; st >>= 1) {
        if (tid < st) red[tid] += red[tid + st];
        __syncthreads();
    }
    if (tid == 0) {
        float sv = 1.f / (1.f + expf(-(red[0] + b4[0])));
        g_sent[b] = sv;
        out_sent[b] = sv;
    }
}

// =====================================================================
// Kernel 6: finalize losses.
// =====================================================================
__global__ void __launch_bounds__(64)
final_kernel(float* __restrict__ out)
{
    const int b = threadIdx.x;
    float sl = g_sent[b] - g_slab[b]; sl *= sl;
    float ra = g_minm[b] * g_minm[b];
    float d  = g_maxm[b] - g_slab[b]; float rb = d * d;
    float tl = g_tl[b];

    __shared__ float s1[64], s2[64], s3[64], s4[64];
    s1[b] = sl; s2[b] = tl; s3[b] = ra; s4[b] = rb;
    __syncthreads();
    for (int st = 32; st > 0; st >>= 1) {
        if (b < st) { s1[b] += s1[b+st]; s2[b] += s2[b+st]; s3[b] += s3[b+st]; s4[b] += s4[b+st]; }
        __syncthreads();
    }
    if (b == 0) {
        float sentence = s1[0], token = s2[0], rega = s3[0], regb = s4[0];
        out[0] = sentence + token + 0.01f * (rega + regb);
        out[1] = sentence;
        out[2] = token;
        out[3] = rega;
        out[4] = regb;
    }
}

// =====================================================================
extern "C" void kernel_launch(void* const* d_in, const int* in_sizes, int n_in,
                              void* d_out, int out_size)
{
    const float* hs     = (const float*)d_in[0];
    const int*   off    = (const int*)  d_in[1];
    const float* labels = (const float*)d_in[2];
    const float* W1     = (const float*)d_in[3];
    const float* b1     = (const float*)d_in[4];
    const float* W2     = (const float*)d_in[5];
    const float* b2     = (const float*)d_in[6];
    const float* W3     = (const float*)d_in[7];
    const float* b3     = (const float*)d_in[8];
    const float* W4     = (const float*)d_in[9];
    const float* b4     = (const float*)d_in[10];

    float* out = (float*)d_out;
    float* out_hidden = out + OUT_HID_OFF;
    float* out_masked = out + OUT_MASK_OFF;
    float* out_sent   = out + OUT_SENT_OFF;

    float* tok; cudaGetSymbolAddress((void**)&tok, g_token_att);

    // Stage A: token attention head (TF32 MMA) + hidden echo
    att_gemm_kernel<<<NTOK / MT, 256>>>(hs, W1, b1, W2, b2, tok, out_hidden);

    // Stage B: segment max, mask, row stats
    seg_mask_kernel<<<BATCH, SEQ>>>(off, labels, tok, out_masked);

    // Stage C: pooling partials (s-split)
    dim3 pg(BATCH, 4);
    pool_kernel<<<pg, 192>>>(hs, out_masked);

    // Stage D: sentence head partials (k-split)
    dim3 sg(BATCH, 8);
    sent_part_kernel<<<sg, 320>>>(W3);

    // Stage E: sentence combine
    sent_comb_kernel<<<BATCH, 320>>>(b3, W4, b4, out_sent);

    // Stage F: losses
    final_kernel<<<1, 64>>>(out);
}

// round 6
// speedup vs baseline: 3.7999x; 1.3461x over previous
#include <cuda_runtime.h>
#include <cuda_bf16.h>
#include <math.h>

// Problem dims
#define BATCH 64
#define SEQ   512
#define HID   768
#define ATTH  100
#define CLSH  300

#define NTOK (BATCH*SEQ)          // 32768
#define HS_ELEMS (BATCH*SEQ*HID)  // 25165824

// Output layout
#define OUT_HID_OFF  5
#define OUT_MASK_OFF (5 + HS_ELEMS)
#define OUT_SENT_OFF (5 + HS_ELEMS + NTOK)

// ---------------- device scratch ----------------
__device__ float g_token_att[NTOK];
__device__ float g_pool_part[4 * BATCH * HID];
__device__ float g_sent_j[BATCH * 8 * CLSH];
__device__ float g_sum[BATCH];
__device__ float g_maxm[BATCH];
__device__ float g_minm[BATCH];
__device__ float g_slab[BATCH];
__device__ float g_tl[BATCH];
__device__ float g_sent[BATCH];

__device__ __forceinline__ void mma_tf32(float& d0, float& d1, float& d2, float& d3,
                                         unsigned a0, unsigned a1, unsigned a2, unsigned a3,
                                         unsigned b0, unsigned b1) {
    asm volatile(
        "mma.sync.aligned.m16n8k8.row.col.f32.tf32.tf32.f32 "
        "{%0,%1,%2,%3}, {%4,%5,%6,%7}, {%8,%9}, {%0,%1,%2,%3};"
        : "+f"(d0), "+f"(d1), "+f"(d2), "+f"(d3)
        : "r"(a0), "r"(a1), "r"(a2), "r"(a3), "r"(b0), "r"(b1));
}

__device__ __forceinline__ void cp16(float* smem_dst, const float* gsrc) {
    unsigned s = (unsigned)__cvta_generic_to_shared(smem_dst);
    asm volatile("cp.async.cg.shared.global [%0], [%1], 16;" :: "r"(s), "l"(gsrc));
}
__device__ __forceinline__ void cp_commit() {
    asm volatile("cp.async.commit_group;");
}
__device__ __forceinline__ void cp_wait1() {
    asm volatile("cp.async.wait_group 1;");
}

// =====================================================================
// Kernel 1: token-attention head, tf32 MMA, cp.async 3-stage pipeline.
// Raw fp32 bits fed to HMMA.TF32 (HW truncates mantissa; no CVT pass).
// =====================================================================
#define MT     128
#define KT     32
#define NT     13
#define KCH    (HID / KT)      // 24
#define ASTR   36              // A row stride (floats): conflict-free, 144B = 16B mult.
#define WSTR   104             // W row stride (floats): conflict-free, 416B = 16B mult.
#define STAGES 3
#define A_TILE_FL (MT * ASTR)  // 4608
#define W_TILE_FL (KT * WSTR)  // 3328
#define ATT_SMEM_BYTES (STAGES * (A_TILE_FL + W_TILE_FL) * 4)   // 95232

__global__ void __launch_bounds__(256)
att_gemm_kernel(const float* __restrict__ A,
                const float* __restrict__ W1,
                const float* __restrict__ b1,
                const float* __restrict__ W2,
                const float* __restrict__ b2,
                float* __restrict__ tok)
{
    extern __shared__ float sm[];
    float* Abuf = sm;                          // [STAGES][MT][ASTR]
    float* Wbuf = sm + STAGES * A_TILE_FL;     // [STAGES][KT][WSTR]

    const int tid  = threadIdx.x;
    const int lane = tid & 31;
    const int wid  = tid >> 5;
    const int q    = lane >> 2;
    const int r4   = lane & 3;
    const int m0   = blockIdx.x * MT;
    const int wr   = wid * 16;

    // zero W pad cols 100..103 in all stages (cp.async never writes them)
    for (int i = tid; i < STAGES * KT * 4; i += 256) {
        int st = i / (KT * 4);
        int r  = (i >> 2) % KT;
        int c  = i & 3;
        Wbuf[st * W_TILE_FL + r * WSTR + ATTH + c] = 0.f;
    }

    float acc[NT][4];
#pragma unroll
    for (int nt = 0; nt < NT; nt++)
#pragma unroll
        for (int c = 0; c < 4; c++) acc[nt][c] = 0.f;

    auto issue = [&](int st, int k0) {
        float* As = Abuf + st * A_TILE_FL;
        float* Ws = Wbuf + st * W_TILE_FL;
        // A tile: 128 rows x 32 floats = 1024 x 16B chunks
#pragma unroll
        for (int i = 0; i < 4; i++) {
            int f   = i * 256 + tid;
            int row = f >> 3;
            int c16 = f & 7;
            cp16(As + row * ASTR + c16 * 4,
                 A + (size_t)(m0 + row) * HID + k0 + c16 * 4);
        }
        // W tile: 32 rows x 100 floats = 800 x 16B chunks
#pragma unroll
        for (int i = 0; i < 4; i++) {
            int e = i * 256 + tid;
            if (e < KT * 25) {
                int kr = e / 25;
                int cc = e % 25;
                cp16(Ws + kr * WSTR + cc * 4,
                     W1 + (size_t)(k0 + kr) * ATTH + cc * 4);
            }
        }
    };

    issue(0, 0);       cp_commit();
    issue(1, KT);      cp_commit();

    for (int kc = 0; kc < KCH; kc++) {
        cp_wait1();            // stage kc ready
        __syncthreads();       // visibility + prior-stage consumption complete
        if (kc + 2 < KCH) issue((kc + 2) % STAGES, (kc + 2) * KT);
        cp_commit();           // always commit (possibly empty) to keep group count uniform

        const float* As = Abuf + (kc % STAGES) * A_TILE_FL;
        const float* Ws = Wbuf + (kc % STAGES) * W_TILE_FL;

#pragma unroll
        for (int ks = 0; ks < 4; ks++) {
            const int k = ks * 8;
            unsigned a0 = __float_as_uint(As[(wr + q    ) * ASTR + k + r4]);
            unsigned a1 = __float_as_uint(As[(wr + q + 8) * ASTR + k + r4]);
            unsigned a2 = __float_as_uint(As[(wr + q    ) * ASTR + k + r4 + 4]);
            unsigned a3 = __float_as_uint(As[(wr + q + 8) * ASTR + k + r4 + 4]);
#pragma unroll
            for (int nt = 0; nt < NT; nt++) {
                unsigned b0 = __float_as_uint(Ws[(k + r4    ) * WSTR + nt * 8 + q]);
                unsigned b1 = __float_as_uint(Ws[(k + r4 + 4) * WSTR + nt * 8 + q]);
                mma_tf32(acc[nt][0], acc[nt][1], acc[nt][2], acc[nt][3],
                         a0, a1, a2, a3, b0, b1);
            }
        }
    }

    // Epilogue: rows (wr+q, wr+q+8), cols j = nt*8 + 2*r4 + {0,1}
    const float bias2 = b2[0];
    float p0 = 0.f, p1 = 0.f;
#pragma unroll
    for (int nt = 0; nt < NT; nt++) {
        int j0 = nt * 8 + 2 * r4;
        int j1 = j0 + 1;
        float bb0 = 0.f, bb1 = 0.f, ww0 = 0.f, ww1 = 0.f;
        if (j0 < ATTH) { bb0 = b1[j0]; ww0 = W2[j0]; }
        if (j1 < ATTH) { bb1 = b1[j1]; ww1 = W2[j1]; }
        p0 += tanhf(acc[nt][0] + bb0) * ww0 + tanhf(acc[nt][1] + bb1) * ww1;
        p1 += tanhf(acc[nt][2] + bb0) * ww0 + tanhf(acc[nt][3] + bb1) * ww1;
    }
#pragma unroll
    for (int o = 1; o <= 2; o <<= 1) {
        p0 += __shfl_xor_sync(0xffffffffu, p0, o);
        p1 += __shfl_xor_sync(0xffffffffu, p1, o);
    }
    if (r4 == 0) {
        int m = m0 + wr + q;
        tok[m]     = 1.f / (1.f + expf(-(p0 + bias2)));
        tok[m + 8] = 1.f / (1.f + expf(-(p1 + bias2)));
    }
}

// =====================================================================
// Kernel 2: segment-max + mask + per-row stats (warp-shuffle reductions).
// =====================================================================
__global__ void __launch_bounds__(512)
seg_mask_kernel(const int* __restrict__ off,
                const float* __restrict__ labels,
                const float* __restrict__ tok,
                float* __restrict__ out_masked)
{
    const int b = blockIdx.x;
    const int s = threadIdx.x;
    const int lane = s & 31;
    const int warp = s >> 5;
    const int base = b * SEQ;

    float lab  = labels[base + s];
    bool  cont = (off[(size_t)(base + s) * 2] != 0);

    float masked = 0.f;
    if (!cont) {
        float wa = tok[base + s];
        int t = s + 1;
        while (t < SEQ && off[(size_t)(base + t) * 2] != 0) {
            wa = fmaxf(wa, tok[base + t]);
            t++;
        }
        if (lab != -1.0f) masked = wa;
    }
    out_masked[base + s] = masked;

    float z = (lab == 1.0f) ? 1.0f : 0.0f;
    float v_sum = masked;
    float v_max = masked;
    float v_min = (masked == 0.f) ? 1.f : masked;
    float v_lab = lab;
    float v_tl  = (masked - z) * (masked - z);

#pragma unroll
    for (int o = 16; o > 0; o >>= 1) {
        v_sum += __shfl_xor_sync(0xffffffffu, v_sum, o);
        v_max = fmaxf(v_max, __shfl_xor_sync(0xffffffffu, v_max, o));
        v_min = fminf(v_min, __shfl_xor_sync(0xffffffffu, v_min, o));
        v_lab = fmaxf(v_lab, __shfl_xor_sync(0xffffffffu, v_lab, o));
        v_tl  += __shfl_xor_sync(0xffffffffu, v_tl, o);
    }

    __shared__ float ws[16][5];
    if (lane == 0) {
        ws[warp][0] = v_sum; ws[warp][1] = v_max; ws[warp][2] = v_min;
        ws[warp][3] = v_lab; ws[warp][4] = v_tl;
    }
    __syncthreads();

    if (warp == 0) {
        float a0 = (lane < 16) ? ws[lane][0] : 0.f;
        float a1 = (lane < 16) ? ws[lane][1] : -1e30f;
        float a2 = (lane < 16) ? ws[lane][2] :  1e30f;
        float a3 = (lane < 16) ? ws[lane][3] : -1e30f;
        float a4 = (lane < 16) ? ws[lane][4] : 0.f;
#pragma unroll
        for (int o = 8; o > 0; o >>= 1) {
            a0 += __shfl_xor_sync(0xffffffffu, a0, o);
            a1 = fmaxf(a1, __shfl_xor_sync(0xffffffffu, a1, o));
            a2 = fminf(a2, __shfl_xor_sync(0xffffffffu, a2, o));
            a3 = fmaxf(a3, __shfl_xor_sync(0xffffffffu, a3, o));
            a4 += __shfl_xor_sync(0xffffffffu, a4, o);
        }
        if (lane == 0) {
            g_sum[b] = a0; g_maxm[b] = a1; g_minm[b] = a2;
            g_slab[b] = a3; g_tl[b] = a4;
        }
    }
}

// =====================================================================
// Kernel 3: pooling partials + hidden echo. grid (BATCH, 4), 192 threads.
// =====================================================================
__global__ void __launch_bounds__(192)
pool_kernel(const float* __restrict__ hs,
            const float* __restrict__ masked,
            float* __restrict__ out_hidden)
{
    const int b  = blockIdx.x;
    const int ss = blockIdx.y;
    const int tid = threadIdx.x;
    const int s0 = ss * 128;

    __shared__ float nm[128];
    if (tid < 128) nm[tid] = masked[b * SEQ + s0 + tid];
    __syncthreads();

    const size_t rowbase = (size_t)b * SEQ * HID + (size_t)s0 * HID;
    const float4* hp = reinterpret_cast<const float4*>(hs + rowbase) + tid;
    float* op = out_hidden + rowbase + tid * 4;

    float4 acc = make_float4(0.f, 0.f, 0.f, 0.f);
#pragma unroll 8
    for (int s = 0; s < 128; s++) {
        float4 v = hp[(size_t)s * (HID / 4)];
        // echo (out_hidden only 4B aligned -> scalar stores)
        float* o = op + (size_t)s * HID;
        o[0] = v.x; o[1] = v.y; o[2] = v.z; o[3] = v.w;
        float w = nm[s];
        acc.x += v.x * w; acc.y += v.y * w;
        acc.z += v.z * w; acc.w += v.w * w;
    }

    float4* dst = reinterpret_cast<float4*>(
        g_pool_part + ((size_t)ss * BATCH + b) * HID) + tid;
    *dst = acc;
}

// =====================================================================
// Kernel 4: sentence head split-k partials. grid (BATCH, 8), 320 threads.
// =====================================================================
__global__ void __launch_bounds__(320)
sent_part_kernel(const float* __restrict__ W3)
{
    const int b  = blockIdx.x;
    const int ks = blockIdx.y;
    const int tid = threadIdx.x;
    const int k0 = ks * 96;

    __shared__ float pl[96];
    if (tid < 96) {
        const int h = k0 + tid;
        float v = g_pool_part[(size_t)(0 * BATCH + b) * HID + h]
                + g_pool_part[(size_t)(1 * BATCH + b) * HID + h]
                + g_pool_part[(size_t)(2 * BATCH + b) * HID + h]
                + g_pool_part[(size_t)(3 * BATCH + b) * HID + h];
        pl[tid] = v / g_sum[b];
    }
    __syncthreads();

    if (tid < CLSH) {
        const float* wp = W3 + (size_t)k0 * CLSH + tid;
        float a0 = 0.f, a1 = 0.f;
#pragma unroll 8
        for (int k = 0; k < 96; k += 2) {
            a0 += pl[k]     * wp[(size_t)k * CLSH];
            a1 += pl[k + 1] * wp[(size_t)(k + 1) * CLSH];
        }
        g_sent_j[((size_t)b * 8 + ks) * CLSH + tid] = a0 + a1;
    }
}

// =====================================================================
// Kernel 5: sentence combine. grid (BATCH), 320 threads.
// =====================================================================
__global__ void __launch_bounds__(320)
sent_comb_kernel(const float* __restrict__ b3,
                 const float* __restrict__ W4,
                 const float* __restrict__ b4,
                 float* __restrict__ out_sent)
{
    const int b = blockIdx.x;
    const int tid = threadIdx.x;

    float v = 0.f;
    if (tid < CLSH) {
        float s = b3[tid];
#pragma unroll
        for (int ks = 0; ks < 8; ks++)
            s += g_sent_j[((size_t)b * 8 + ks) * CLSH + tid];
        v = tanhf(s) * W4[tid];
    }

    __shared__ float red[512];
    red[tid] = v;
    if (tid + 320 < 512) red[tid + 320] = 0.f;
    __syncthreads();
    for (int st = 256; st > 0; st >>= 1) {
        if (tid < st) red[tid] += red[tid + st];
        __syncthreads();
    }
    if (tid == 0) {
        float sv = 1.f / (1.f + expf(-(red[0] + b4[0])));
        g_sent[b] = sv;
        out_sent[b] = sv;
    }
}

// =====================================================================
// Kernel 6: finalize losses.
// =====================================================================
__global__ void __launch_bounds__(64)
final_kernel(float* __restrict__ out)
{
    const int b = threadIdx.x;
    float sl = g_sent[b] - g_slab[b]; sl *= sl;
    float ra = g_minm[b] * g_minm[b];
    float d  = g_maxm[b] - g_slab[b]; float rb = d * d;
    float tl = g_tl[b];

    __shared__ float s1[64], s2[64], s3[64], s4[64];
    s1[b] = sl; s2[b] = tl; s3[b] = ra; s4[b] = rb;
    __syncthreads();
    for (int st = 32; st > 0; st >>= 1) {
        if (b < st) { s1[b] += s1[b+st]; s2[b] += s2[b+st]; s3[b] += s3[b+st]; s4[b] += s4[b+st]; }
        __syncthreads();
    }
    if (b == 0) {
        float sentence = s1[0], token = s2[0], rega = s3[0], regb = s4[0];
        out[0] = sentence + token + 0.01f * (rega + regb);
        out[1] = sentence;
        out[2] = token;
        out[3] = rega;
        out[4] = regb;
    }
}

// =====================================================================
extern "C" void kernel_launch(void* const* d_in, const int* in_sizes, int n_in,
                              void* d_out, int out_size)
{
    const float* hs     = (const float*)d_in[0];
    const int*   off    = (const int*)  d_in[1];
    const float* labels = (const float*)d_in[2];
    const float* W1     = (const float*)d_in[3];
    const float* b1     = (const float*)d_in[4];
    const float* W2     = (const float*)d_in[5];
    const float* b2     = (const float*)d_in[6];
    const float* W3     = (const float*)d_in[7];
    const float* b3     = (const float*)d_in[8];
    const float* W4     = (const float*)d_in[9];
    const float* b4     = (const float*)d_in[10];

    float* out = (float*)d_out;
    float* out_hidden = out + OUT_HID_OFF;
    float* out_masked = out + OUT_MASK_OFF;
    float* out_sent   = out + OUT_SENT_OFF;

    float* tok; cudaGetSymbolAddress((void**)&tok, g_token_att);

    cudaFuncSetAttribute(att_gemm_kernel,
                         cudaFuncAttributeMaxDynamicSharedMemorySize,
                         ATT_SMEM_BYTES);

    // Stage A: token attention head (TF32 MMA, cp.async pipeline)
    att_gemm_kernel<<<NTOK / MT, 256, ATT_SMEM_BYTES>>>(hs, W1, b1, W2, b2, tok);

    // Stage B: segment max, mask, row stats
    seg_mask_kernel<<<BATCH, SEQ>>>(off, labels, tok, out_masked);

    // Stage C: pooling partials + hidden echo
    dim3 pg(BATCH, 4);
    pool_kernel<<<pg, 192>>>(hs, out_masked, out_hidden);

    // Stage D: sentence head partials (k-split)
    dim3 sg(BATCH, 8);
    sent_part_kernel<<<sg, 320>>>(W3);

    // Stage E: sentence combine
    sent_comb_kernel<<<BATCH, 320>>>(b3, W4, b4, out_sent);

    // Stage F: losses
    final_kernel<<<1, 64>>>(out);
}

// round 7
// speedup vs baseline: 3.8633x; 1.0167x over previous
#include <cuda_runtime.h>
#include <cuda_bf16.h>
#include <math.h>

// Problem dims
#define BATCH 64
#define SEQ   512
#define HID   768
#define ATTH  100
#define CLSH  300

#define NTOK (BATCH*SEQ)          // 32768
#define HS_ELEMS (BATCH*SEQ*HID)  // 25165824

// Output layout
#define OUT_HID_OFF  5
#define OUT_MASK_OFF (5 + HS_ELEMS)
#define OUT_SENT_OFF (5 + HS_ELEMS + NTOK)

#define PSPLIT 8                  // pooling s-splits

// ---------------- device scratch ----------------
__device__ float g_token_att[NTOK];
__device__ float g_pool_part[PSPLIT * BATCH * HID];
__device__ float g_sent_j[BATCH * 8 * CLSH];
__device__ float g_sum[BATCH];
__device__ float g_maxm[BATCH];
__device__ float g_minm[BATCH];
__device__ float g_slab[BATCH];
__device__ float g_tl[BATCH];
__device__ float g_sent[BATCH];

__device__ __forceinline__ void mma_tf32(float& d0, float& d1, float& d2, float& d3,
                                         unsigned a0, unsigned a1, unsigned a2, unsigned a3,
                                         unsigned b0, unsigned b1) {
    asm volatile(
        "mma.sync.aligned.m16n8k8.row.col.f32.tf32.tf32.f32 "
        "{%0,%1,%2,%3}, {%4,%5,%6,%7}, {%8,%9}, {%0,%1,%2,%3};"
        : "+f"(d0), "+f"(d1), "+f"(d2), "+f"(d3)
        : "r"(a0), "r"(a1), "r"(a2), "r"(a3), "r"(b0), "r"(b1));
}

__device__ __forceinline__ void cp16(float* smem_dst, const float* gsrc) {
    unsigned s = (unsigned)__cvta_generic_to_shared(smem_dst);
    asm volatile("cp.async.cg.shared.global [%0], [%1], 16;" :: "r"(s), "l"(gsrc));
}
__device__ __forceinline__ void cp_commit() {
    asm volatile("cp.async.commit_group;");
}
__device__ __forceinline__ void cp_wait1() {
    asm volatile("cp.async.wait_group 1;");
}

// =====================================================================
// Kernel 1: token-attention head, tf32 MMA, cp.async pipeline.
// MT=256 rows/block, warp owns M=32 (two m16 tiles) x all 104 cols.
// =====================================================================
#define MT     256
#define KT     32
#define NT     13
#define KCH    (HID / KT)      // 24
#define ASTR   36
#define WSTR   104
#define STAGES 3
#define A_TILE_FL (MT * ASTR)  // 9216
#define W_TILE_FL (KT * WSTR)  // 3328
#define ATT_SMEM_BYTES (STAGES * (A_TILE_FL + W_TILE_FL) * 4)   // 150528

__global__ void __launch_bounds__(256)
att_gemm_kernel(const float* __restrict__ A,
                const float* __restrict__ W1,
                const float* __restrict__ b1,
                const float* __restrict__ W2,
                const float* __restrict__ b2,
                float* __restrict__ tok)
{
    extern __shared__ float sm[];
    float* Abuf = sm;                          // [STAGES][MT][ASTR]
    float* Wbuf = sm + STAGES * A_TILE_FL;     // [STAGES][KT][WSTR]

    const int tid  = threadIdx.x;
    const int lane = tid & 31;
    const int wid  = tid >> 5;
    const int q    = lane >> 2;
    const int r4   = lane & 3;
    const int m0   = blockIdx.x * MT;
    const int wr   = wid * 32;

    // zero W pad cols 100..103 in all stages
    for (int i = tid; i < STAGES * KT * 4; i += 256) {
        int st = i / (KT * 4);
        int r  = (i >> 2) % KT;
        int c  = i & 3;
        Wbuf[st * W_TILE_FL + r * WSTR + ATTH + c] = 0.f;
    }

    float acc0[NT][4], acc1[NT][4];
#pragma unroll
    for (int nt = 0; nt < NT; nt++)
#pragma unroll
        for (int c = 0; c < 4; c++) { acc0[nt][c] = 0.f; acc1[nt][c] = 0.f; }

    auto issue = [&](int st, int k0) {
        float* As = Abuf + st * A_TILE_FL;
        float* Ws = Wbuf + st * W_TILE_FL;
        // A tile: 256 rows x 32 floats = 2048 x 16B chunks
#pragma unroll
        for (int i = 0; i < 8; i++) {
            int f   = i * 256 + tid;
            int row = f >> 3;
            int c16 = f & 7;
            cp16(As + row * ASTR + c16 * 4,
                 A + (size_t)(m0 + row) * HID + k0 + c16 * 4);
        }
        // W tile: 32 rows x 100 floats = 800 x 16B chunks
#pragma unroll
        for (int i = 0; i < 4; i++) {
            int e = i * 256 + tid;
            if (e < KT * 25) {
                int kr = e / 25;
                int cc = e % 25;
                cp16(Ws + kr * WSTR + cc * 4,
                     W1 + (size_t)(k0 + kr) * ATTH + cc * 4);
            }
        }
    };

    issue(0, 0);       cp_commit();
    issue(1, KT);      cp_commit();

    for (int kc = 0; kc < KCH; kc++) {
        cp_wait1();
        __syncthreads();
        if (kc + 2 < KCH) issue((kc + 2) % STAGES, (kc + 2) * KT);
        cp_commit();

        const float* As = Abuf + (kc % STAGES) * A_TILE_FL;
        const float* Ws = Wbuf + (kc % STAGES) * W_TILE_FL;

#pragma unroll
        for (int ks = 0; ks < 4; ks++) {
            const int k = ks * 8;
            // tile 0: rows wr+q, wr+q+8
            unsigned a00 = __float_as_uint(As[(wr + q     ) * ASTR + k + r4]);
            unsigned a01 = __float_as_uint(As[(wr + q + 8 ) * ASTR + k + r4]);
            unsigned a02 = __float_as_uint(As[(wr + q     ) * ASTR + k + r4 + 4]);
            unsigned a03 = __float_as_uint(As[(wr + q + 8 ) * ASTR + k + r4 + 4]);
            // tile 1: rows wr+16+q, wr+24+q
            unsigned a10 = __float_as_uint(As[(wr + q + 16) * ASTR + k + r4]);
            unsigned a11 = __float_as_uint(As[(wr + q + 24) * ASTR + k + r4]);
            unsigned a12 = __float_as_uint(As[(wr + q + 16) * ASTR + k + r4 + 4]);
            unsigned a13 = __float_as_uint(As[(wr + q + 24) * ASTR + k + r4 + 4]);
#pragma unroll
            for (int nt = 0; nt < NT; nt++) {
                unsigned b0 = __float_as_uint(Ws[(k + r4    ) * WSTR + nt * 8 + q]);
                unsigned b1 = __float_as_uint(Ws[(k + r4 + 4) * WSTR + nt * 8 + q]);
                mma_tf32(acc0[nt][0], acc0[nt][1], acc0[nt][2], acc0[nt][3],
                         a00, a01, a02, a03, b0, b1);
                mma_tf32(acc1[nt][0], acc1[nt][1], acc1[nt][2], acc1[nt][3],
                         a10, a11, a12, a13, b0, b1);
            }
        }
    }

    // Epilogue: rows (wr+q, wr+q+8, wr+16+q, wr+24+q), cols j = nt*8+2r4+{0,1}
    const float bias2 = b2[0];
    float p0 = 0.f, p1 = 0.f, p2 = 0.f, p3 = 0.f;
#pragma unroll
    for (int nt = 0; nt < NT; nt++) {
        int j0 = nt * 8 + 2 * r4;
        int j1 = j0 + 1;
        float bb0 = 0.f, bb1 = 0.f, ww0 = 0.f, ww1 = 0.f;
        if (j0 < ATTH) { bb0 = b1[j0]; ww0 = W2[j0]; }
        if (j1 < ATTH) { bb1 = b1[j1]; ww1 = W2[j1]; }
        p0 += tanhf(acc0[nt][0] + bb0) * ww0 + tanhf(acc0[nt][1] + bb1) * ww1;
        p1 += tanhf(acc0[nt][2] + bb0) * ww0 + tanhf(acc0[nt][3] + bb1) * ww1;
        p2 += tanhf(acc1[nt][0] + bb0) * ww0 + tanhf(acc1[nt][1] + bb1) * ww1;
        p3 += tanhf(acc1[nt][2] + bb0) * ww0 + tanhf(acc1[nt][3] + bb1) * ww1;
    }
#pragma unroll
    for (int o = 1; o <= 2; o <<= 1) {
        p0 += __shfl_xor_sync(0xffffffffu, p0, o);
        p1 += __shfl_xor_sync(0xffffffffu, p1, o);
        p2 += __shfl_xor_sync(0xffffffffu, p2, o);
        p3 += __shfl_xor_sync(0xffffffffu, p3, o);
    }
    if (r4 == 0) {
        int m = m0 + wr + q;
        tok[m]      = 1.f / (1.f + expf(-(p0 + bias2)));
        tok[m + 8]  = 1.f / (1.f + expf(-(p1 + bias2)));
        tok[m + 16] = 1.f / (1.f + expf(-(p2 + bias2)));
        tok[m + 24] = 1.f / (1.f + expf(-(p3 + bias2)));
    }
}

// =====================================================================
// Kernel 2: segment-max + mask + per-row stats (warp-shuffle reductions).
// =====================================================================
__global__ void __launch_bounds__(512)
seg_mask_kernel(const int* __restrict__ off,
                const float* __restrict__ labels,
                const float* __restrict__ tok,
                float* __restrict__ out_masked)
{
    const int b = blockIdx.x;
    const int s = threadIdx.x;
    const int lane = s & 31;
    const int warp = s >> 5;
    const int base = b * SEQ;

    float lab  = labels[base + s];
    bool  cont = (off[(size_t)(base + s) * 2] != 0);

    float masked = 0.f;
    if (!cont) {
        float wa = tok[base + s];
        int t = s + 1;
        while (t < SEQ && off[(size_t)(base + t) * 2] != 0) {
            wa = fmaxf(wa, tok[base + t]);
            t++;
        }
        if (lab != -1.0f) masked = wa;
    }
    out_masked[base + s] = masked;

    float z = (lab == 1.0f) ? 1.0f : 0.0f;
    float v_sum = masked;
    float v_max = masked;
    float v_min = (masked == 0.f) ? 1.f : masked;
    float v_lab = lab;
    float v_tl  = (masked - z) * (masked - z);

#pragma unroll
    for (int o = 16; o > 0; o >>= 1) {
        v_sum += __shfl_xor_sync(0xffffffffu, v_sum, o);
        v_max = fmaxf(v_max, __shfl_xor_sync(0xffffffffu, v_max, o));
        v_min = fminf(v_min, __shfl_xor_sync(0xffffffffu, v_min, o));
        v_lab = fmaxf(v_lab, __shfl_xor_sync(0xffffffffu, v_lab, o));
        v_tl  += __shfl_xor_sync(0xffffffffu, v_tl, o);
    }

    __shared__ float ws[16][5];
    if (lane == 0) {
        ws[warp][0] = v_sum; ws[warp][1] = v_max; ws[warp][2] = v_min;
        ws[warp][3] = v_lab; ws[warp][4] = v_tl;
    }
    __syncthreads();

    if (warp == 0) {
        float a0 = (lane < 16) ? ws[lane][0] : 0.f;
        float a1 = (lane < 16) ? ws[lane][1] : -1e30f;
        float a2 = (lane < 16) ? ws[lane][2] :  1e30f;
        float a3 = (lane < 16) ? ws[lane][3] : -1e30f;
        float a4 = (lane < 16) ? ws[lane][4] : 0.f;
#pragma unroll
        for (int o = 8; o > 0; o >>= 1) {
            a0 += __shfl_xor_sync(0xffffffffu, a0, o);
            a1 = fmaxf(a1, __shfl_xor_sync(0xffffffffu, a1, o));
            a2 = fminf(a2, __shfl_xor_sync(0xffffffffu, a2, o));
            a3 = fmaxf(a3, __shfl_xor_sync(0xffffffffu, a3, o));
            a4 += __shfl_xor_sync(0xffffffffu, a4, o);
        }
        if (lane == 0) {
            g_sum[b] = a0; g_maxm[b] = a1; g_minm[b] = a2;
            g_slab[b] = a3; g_tl[b] = a4;
        }
    }
}

// =====================================================================
// Kernel 3: pooling partials + hidden echo. grid (BATCH, PSPLIT), 192 thr.
// =====================================================================
__global__ void __launch_bounds__(192)
pool_kernel(const float* __restrict__ hs,
            const float* __restrict__ masked,
            float* __restrict__ out_hidden)
{
    const int b  = blockIdx.x;
    const int ss = blockIdx.y;
    const int tid = threadIdx.x;
    const int SCH = SEQ / PSPLIT;              // 64
    const int s0 = ss * SCH;

    __shared__ float nm[SCH];
    if (tid < SCH) nm[tid] = masked[b * SEQ + s0 + tid];
    __syncthreads();

    const size_t rowbase = (size_t)b * SEQ * HID + (size_t)s0 * HID;
    const float4* hp = reinterpret_cast<const float4*>(hs + rowbase) + tid;
    float* op = out_hidden + rowbase + tid * 4;

    float4 acc = make_float4(0.f, 0.f, 0.f, 0.f);
#pragma unroll 8
    for (int s = 0; s < SCH; s++) {
        float4 v = hp[(size_t)s * (HID / 4)];
        float* o = op + (size_t)s * HID;       // out_hidden only 4B aligned
        o[0] = v.x; o[1] = v.y; o[2] = v.z; o[3] = v.w;
        float w = nm[s];
        acc.x += v.x * w; acc.y += v.y * w;
        acc.z += v.z * w; acc.w += v.w * w;
    }

    float4* dst = reinterpret_cast<float4*>(
        g_pool_part + ((size_t)ss * BATCH + b) * HID) + tid;
    *dst = acc;
}

// =====================================================================
// Kernel 4: sentence head split-k partials. grid (BATCH, 8), 320 threads.
// =====================================================================
__global__ void __launch_bounds__(320)
sent_part_kernel(const float* __restrict__ W3)
{
    const int b  = blockIdx.x;
    const int ks = blockIdx.y;
    const int tid = threadIdx.x;
    const int k0 = ks * 96;

    __shared__ float pl[96];
    if (tid < 96) {
        const int h = k0 + tid;
        float v = 0.f;
#pragma unroll
        for (int ss = 0; ss < PSPLIT; ss++)
            v += g_pool_part[((size_t)ss * BATCH + b) * HID + h];
        pl[tid] = v / g_sum[b];
    }
    __syncthreads();

    if (tid < CLSH) {
        const float* wp = W3 + (size_t)k0 * CLSH + tid;
        float a0 = 0.f, a1 = 0.f;
#pragma unroll 8
        for (int k = 0; k < 96; k += 2) {
            a0 += pl[k]     * wp[(size_t)k * CLSH];
            a1 += pl[k + 1] * wp[(size_t)(k + 1) * CLSH];
        }
        g_sent_j[((size_t)b * 8 + ks) * CLSH + tid] = a0 + a1;
    }
}

// =====================================================================
// Kernel 5: sentence combine. grid (BATCH), 320 threads.
// =====================================================================
__global__ void __launch_bounds__(320)
sent_comb_kernel(const float* __restrict__ b3,
                 const float* __restrict__ W4,
                 const float* __restrict__ b4,
                 float* __restrict__ out_sent)
{
    const int b = blockIdx.x;
    const int tid = threadIdx.x;

    float v = 0.f;
    if (tid < CLSH) {
        float s = b3[tid];
#pragma unroll
        for (int ks = 0; ks < 8; ks++)
            s += g_sent_j[((size_t)b * 8 + ks) * CLSH + tid];
        v = tanhf(s) * W4[tid];
    }

    __shared__ float red[512];
    red[tid] = v;
    if (tid + 320 < 512) red[tid + 320] = 0.f;
    __syncthreads();
    for (int st = 256; st > 0; st >>= 1) {
        if (tid < st) red[tid] += red[tid + st];
        __syncthreads();
    }
    if (tid == 0) {
        float sv = 1.f / (1.f + expf(-(red[0] + b4[0])));
        g_sent[b] = sv;
        out_sent[b] = sv;
    }
}

// =====================================================================
// Kernel 6: finalize losses.
// =====================================================================
__global__ void __launch_bounds__(64)
final_kernel(float* __restrict__ out)
{
    const int b = threadIdx.x;
    float sl = g_sent[b] - g_slab[b]; sl *= sl;
    float ra = g_minm[b] * g_minm[b];
    float d  = g_maxm[b] - g_slab[b]; float rb = d * d;
    float tl = g_tl[b];

    __shared__ float s1[64], s2[64], s3[64], s4[64];
    s1[b] = sl; s2[b] = tl; s3[b] = ra; s4[b] = rb;
    __syncthreads();
    for (int st = 32; st > 0; st >>= 1) {
        if (b < st) { s1[b] += s1[b+st]; s2[b] += s2[b+st]; s3[b] += s3[b+st]; s4[b] += s4[b+st]; }
        __syncthreads();
    }
    if (b == 0) {
        float sentence = s1[0], token = s2[0], rega = s3[0], regb = s4[0];
        out[0] = sentence + token + 0.01f * (rega + regb);
        out[1] = sentence;
        out[2] = token;
        out[3] = rega;
        out[4] = regb;
    }
}

// =====================================================================
extern "C" void kernel_launch(void* const* d_in, const int* in_sizes, int n_in,
                              void* d_out, int out_size)
{
    const float* hs     = (const float*)d_in[0];
    const int*   off    = (const int*)  d_in[1];
    const float* labels = (const float*)d_in[2];
    const float* W1     = (const float*)d_in[3];
    const float* b1     = (const float*)d_in[4];
    const float* W2     = (const float*)d_in[5];
    const float* b2     = (const float*)d_in[6];
    const float* W3     = (const float*)d_in[7];
    const float* b3     = (const float*)d_in[8];
    const float* W4     = (const float*)d_in[9];
    const float* b4     = (const float*)d_in[10];

    float* out = (float*)d_out;
    float* out_hidden = out + OUT_HID_OFF;
    float* out_masked = out + OUT_MASK_OFF;
    float* out_sent   = out + OUT_SENT_OFF;

    float* tok; cudaGetSymbolAddress((void**)&tok, g_token_att);

    cudaFuncSetAttribute(att_gemm_kernel,
                         cudaFuncAttributeMaxDynamicSharedMemorySize,
                         ATT_SMEM_BYTES);

    // Stage A: token attention head (TF32 MMA, cp.async, M=32/warp)
    att_gemm_kernel<<<NTOK / MT, 256, ATT_SMEM_BYTES>>>(hs, W1, b1, W2, b2, tok);

    // Stage B: segment max, mask, row stats
    seg_mask_kernel<<<BATCH, SEQ>>>(off, labels, tok, out_masked);

    // Stage C: pooling partials + hidden echo
    dim3 pg(BATCH, PSPLIT);
    pool_kernel<<<pg, 192>>>(hs, out_masked, out_hidden);

    // Stage D: sentence head partials (k-split)
    dim3 sg(BATCH, 8);
    sent_part_kernel<<<sg, 320>>>(W3);

    // Stage E: sentence combine
    sent_comb_kernel<<<BATCH, 320>>>(b3, W4, b4, out_sent);

    // Stage F: losses
    final_kernel<<<1, 64>>>(out);
}